// round 14
// baseline (speedup 1.0000x reference)
#include <cuda_runtime.h>

// Casual_Conv1D: 31 chained Conv1d(1,1,k=2) == one 32-tap FIR + scalar bias.
// R14: no input smem, no barriers. Each thread loads its 48-float window
// directly from global (12x LDG.128, MLP=12; x is L2-resident across graph
// replays). Coefs in registers: per-warp shfl compose (overlapped with
// in-flight LDGs), inner-loop broadcast via __shfl_sync. Only output staging
// uses smem (coalesced STG). ~630 instr/thread vs ~700 for the smem path.

#define B_     128
#define L_     16384
#define NL_    31
#define LOUT_  (L_ - NL_)         // 16353
#define TPB_   128
#define WTILE_ 512                // outputs per warp

__global__ void __launch_bounds__(TPB_)
fir_kernel(const float* __restrict__ x, const float* __restrict__ W,
           const float* __restrict__ b, float* __restrict__ y) {
    __shared__ float sout_[4][544];   // per-warp staging: phys = 17*lane + j

    const int lane = threadIdx.x & 31;
    const int w    = threadIdx.x >> 5;
    const int row  = blockIdx.y;
    const int wtile0 = blockIdx.x * 2048 + w * WTILE_;   // warp's first output
    const bool lastw = (wtile0 == 15872);                // only OOB-halo warp

    // ---- 12x LDG.128: 48-float window straight into registers ----
    // g0 = wtile0 + 16*lane (16-float aligned). Non-last warps: max idx
    // wtile0+543 <= 15903 < 16384. Last warp: guard at local 512 boundary
    // (inputs [15872,16384) cover all unmasked outputs' taps).
    const float* xw = x + (size_t)row * L_ + wtile0 + 16 * lane;
    float xr[48];
    if (!lastw) {
        #pragma unroll
        for (int j = 0; j < 12; ++j)
            *reinterpret_cast<float4*>(xr + 4 * j) =
                *reinterpret_cast<const float4*>(xw + 4 * j);
    } else {
        #pragma unroll
        for (int j = 0; j < 12; ++j) {
            const int li = 16 * lane + 4 * j;
            *reinterpret_cast<float4*>(xr + 4 * j) =
                (li < 512) ? *reinterpret_cast<const float4*>(xw + 4 * j)
                           : make_float4(0.f, 0.f, 0.f, 0.f);
        }
    }

    // ---- per-warp filter composition (overlaps the LDG latency above) ----
    // lane k ends holding coefficient c[k]; every lane holds bias d.
    float c = (lane == 0) ? W[0] : ((lane == 1) ? W[1] : 0.0f);
    float d = b[0];
    #pragma unroll
    for (int i = 1; i < NL_; ++i) {
        const float w0 = W[2 * i], w1 = W[2 * i + 1];
        float cp = __shfl_up_sync(0xFFFFFFFFu, c, 1);
        if (lane == 0) cp = 0.0f;
        c = w0 * c + w1 * cp;
        d = (w0 + w1) * d + b[i];
    }

    // ---- 512 FFMA from registers; coef broadcast via shfl ----
    float acc[16];
    #pragma unroll
    for (int j = 0; j < 16; ++j) acc[j] = d;

    #pragma unroll
    for (int k = 0; k < 32; ++k) {
        const float ck = __shfl_sync(0xFFFFFFFFu, c, k);
        #pragma unroll
        for (int j = 0; j < 16; ++j)
            acc[j] += ck * xr[j + k];
    }

    // ---- stage outputs: phys(16*lane + j) = 17*lane + j (conflict-free) ---
    {
        float* so = sout_[w] + lane * 17;
        #pragma unroll
        for (int j = 0; j < 16; ++j)
            so[j] = acc[j];
    }
    __syncwarp();

    // ---- coalesced scalar readout: i = lane + 32j, phys = i + i/16 ----
    float* yw = y + (size_t)row * LOUT_ + wtile0 + lane;
    const float* sr = sout_[w] + lane + (lane >> 4);
    if (!lastw) {
        #pragma unroll
        for (int j = 0; j < 16; ++j)
            yw[j * 32] = sr[j * 34];
    } else {                                     // nvalid = 16353-15872 = 481
        #pragma unroll
        for (int j = 0; j < 16; ++j)
            if (lane + j * 32 < 481)
                yw[j * 32] = sr[j * 34];
    }
}

// ---------------------------------------------------------------------------
extern "C" void kernel_launch(void* const* d_in, const int* in_sizes, int n_in,
                              void* d_out, int out_size) {
    const float* x = (const float*)d_in[0];   // (128, 1, 16384) f32
    const float* W = (const float*)d_in[1];   // (31, 2) f32
    const float* b = (const float*)d_in[2];   // (31,)  f32
    float* y = (float*)d_out;                 // (128, 1, 16353) f32

    dim3 grid(8, B_);                         // 1024 blocks, 4096 warps
    fir_kernel<<<grid, TPB_>>>(x, W, b, y);
}

// round 16
// speedup vs baseline: 1.2285x; 1.2285x over previous
#include <cuda_runtime.h>

// Casual_Conv1D: 31 chained Conv1d(1,1,k=2) == one 32-tap FIR + scalar bias.
// R16 (= R15 resubmit after broker infra failure; kernel audited clean).
// Fully vectorized smem on the R11 frame. Pad = +4 per 16 floats
// (stride-20): phys(i) = i + 4*(i>>4) preserves 16B alignment -> LDS.128 /
// STS.128 everywhere, conflict-free (20*l mod 32 spans disjoint 4-bank
// blocks per 8-lane phase). Ring of 20 slots refilled 4-at-a-time.
// Compute-path LDS warp-instructions: 48 scalar -> 12 vector.

#define B_    128
#define L_    16384
#define NL_   31
#define LOUT_ (L_ - NL_)          // 16353
#define R_    16
#define TPB_  128
#define TILE_ (R_ * TPB_)         // 2048
#define PADN_ 2600                // inputs 2080, phys max 2595
#define PADO_ 2560                // outputs 2048, phys max 2555

__global__ void __launch_bounds__(TPB_)
fir_kernel(const float* __restrict__ x, const float* __restrict__ W,
           const float* __restrict__ b, float* __restrict__ y) {
    __shared__ float sbuf[PADN_];     // input tile, phys(i) = i + 4*(i>>4)
    __shared__ float sout[PADO_];     // output staging, same pad rule
    __shared__ float sc[33];          // 32 coefficients + bias at [32]

    const int tid   = threadIdx.x;
    const int row   = blockIdx.y;
    const int tile0 = blockIdx.x * TILE_;
    const float* xrow = x + (size_t)row * L_ + tile0;
    const bool last = (blockIdx.x == 7);          // tile0 = 14336

    // ---- issue all global loads first (latency overlaps compose) ----
    float4 v[4];
    #pragma unroll
    for (int j = 0; j < 4; ++j)
        v[j] = *reinterpret_cast<const float4*>(xrow + tid * 4 + j * 512);
    float4 ve;
    const bool edge = (tid >= 32 && tid < 40);
    if (edge)
        ve = last ? make_float4(0.f, 0.f, 0.f, 0.f)
                  : *reinterpret_cast<const float4*>(xrow + 2048 + (tid - 32) * 4);

    // ---- warp 0: compose 31 k=2 filters while its LDGs are in flight ----
    if (tid < 32) {
        float c = (tid == 0) ? W[0] : ((tid == 1) ? W[1] : 0.0f);
        float d = b[0];
        #pragma unroll
        for (int i = 1; i < NL_; ++i) {
            const float w0 = W[2 * i], w1 = W[2 * i + 1];
            float cp = __shfl_up_sync(0xFFFFFFFFu, c, 1);
            if (tid == 0) cp = 0.0f;
            c = w0 * c + w1 * cp;
            d = (w0 + w1) * d + b[i];
        }
        sc[tid] = c;
        if (tid == 0) sc[32] = d;
    }

    // ---- stage tile with STS.128: phys(4t+512j) = 4t + 4*(t>>2) + 640j ----
    {
        float* sp = sbuf + tid * 4 + 4 * (tid >> 2);
        #pragma unroll
        for (int j = 0; j < 4; ++j)
            *reinterpret_cast<float4*>(sp + 640 * j) = v[j];
    }
    if (edge) {   // i = 2048+4e: phys = 2560 + 4e + 4*(e>>2)
        const int e = tid - 32;
        *reinterpret_cast<float4*>(sbuf + 2560 + 4 * e + 4 * (e >> 2)) = ve;
    }
    __syncthreads();                             // barrier #1

    // ---- 20-slot ring FIR, 16 outputs/thread, LDS.128 refills ----
    // o0 = 16*tid; phys(o0+m) = 20*tid + m + 4*(m>>4); 16B-aligned for m%4==0
    const float* sp = sbuf + tid * 20;
#define XV(m_) (*reinterpret_cast<const float4*>(sp + (m_) + 4 * ((m_) >> 4)))

    float r[20];
    #pragma unroll
    for (int t = 0; t < 20; t += 4) {            // init t = 0..19 (5x LDS.128)
        float4 q = XV(t);
        r[t] = q.x; r[t + 1] = q.y; r[t + 2] = q.z; r[t + 3] = q.w;
    }

    const float bias = sc[32];
    float acc[16];
    #pragma unroll
    for (int j = 0; j < 16; ++j) acc[j] = bias;

    #pragma unroll
    for (int k = 0; k < 32; ++k) {
        if (k >= 4 && (k & 3) == 0) {            // refill t = k+16..k+19
            float4 q = XV(k + 16);
            r[(k + 16) % 20] = q.x;
            r[(k + 17) % 20] = q.y;
            r[(k + 18) % 20] = q.z;
            r[(k + 19) % 20] = q.w;
        }
        const float ck = sc[k];                  // LDS.32 broadcast, imm
        #pragma unroll
        for (int j = 0; j < 16; ++j)
            acc[j] += ck * r[(k + j) % 20];      // compile-time after unroll
    }
#undef XV

    // ---- stage outputs with STS.128: phys(16t + j) = 20t + j ----
    {
        float* so = sout + tid * 20;
        #pragma unroll
        for (int j = 0; j < 16; j += 4)
            *reinterpret_cast<float4*>(so + j) =
                make_float4(acc[j], acc[j + 1], acc[j + 2], acc[j + 3]);
    }
    __syncthreads();                             // barrier #2

    // ---- coalesced scalar readout: i = tid+128j, phys = base + 160j ----
    float* yrow = y + (size_t)row * LOUT_ + tile0 + tid;
    const float* sr = sout + tid + 4 * (tid >> 4);
    if (!last) {
        #pragma unroll
        for (int j = 0; j < R_; ++j)
            yrow[j * 128] = sr[j * 160];
    } else {
        const int nvalid = LOUT_ - tile0;        // 2017
        #pragma unroll
        for (int j = 0; j < R_; ++j)
            if (tid + j * 128 < nvalid)
                yrow[j * 128] = sr[j * 160];
    }
}

// ---------------------------------------------------------------------------
extern "C" void kernel_launch(void* const* d_in, const int* in_sizes, int n_in,
                              void* d_out, int out_size) {
    const float* x = (const float*)d_in[0];   // (128, 1, 16384) f32
    const float* W = (const float*)d_in[1];   // (31, 2) f32
    const float* b = (const float*)d_in[2];   // (31,)  f32
    float* y = (float*)d_out;                 // (128, 1, 16353) f32

    dim3 grid(L_ / TILE_, B_);                // (8, 128) = 1024 blocks
    fir_kernel<<<grid, TPB_>>>(x, W, b, y);
}